// round 9
// baseline (speedup 1.0000x reference)
#include <cuda_runtime.h>
#include <cuda_bf16.h>
#include <cstdint>

#define D 128
#define MAXN 100000
#define NCHUNK 4

// ---- global scratch: X' split into bf16 hi/lo, W transposed split ----
__device__ uint4 g_XpHi4[(size_t)(MAXN + 128) * 16];  // [row][128 bf16] = 256B/row
__device__ uint4 g_XpLo4[(size_t)(MAXN + 128) * 16];
__device__ uint4 g_WtHi4[D * D / 8];                  // [n][k] bf16, 256B/row
__device__ uint4 g_WtLo4[D * D / 8];

// ---- helpers ----
__device__ __forceinline__ void split2(float a, float b, unsigned& hi, unsigned& lo) {
    __nv_bfloat16 ha = __float2bfloat16_rn(a);
    __nv_bfloat16 hb = __float2bfloat16_rn(b);
    float ra = a - __bfloat162float(ha);
    float rb = b - __bfloat162float(hb);
    __nv_bfloat162 hv; hv.x = ha; hv.y = hb;
    __nv_bfloat162 lv = __floats2bfloat162_rn(ra, rb);
    hi = *reinterpret_cast<unsigned*>(&hv);
    lo = *reinterpret_cast<unsigned*>(&lv);
}

__device__ __forceinline__ unsigned smem_u32(const void* p) {
    unsigned a;
    asm("{ .reg .u64 t; cvta.to.shared.u64 t, %1; cvt.u32.u64 %0, t; }"
        : "=r"(a) : "l"(p));
    return a;
}

#define STS128(addr, v)                                                     \
    asm volatile("st.shared.v4.b32 [%0], {%1,%2,%3,%4};" ::"r"(addr),       \
                 "r"((v).x), "r"((v).y), "r"((v).z), "r"((v).w) : "memory")

#define LDSM4(r0, r1, r2, r3, addr)                                         \
    asm volatile("ldmatrix.sync.aligned.m8n8.x4.shared.b16 "                \
                 "{%0,%1,%2,%3}, [%4];"                                     \
                 : "=r"(r0), "=r"(r1), "=r"(r2), "=r"(r3) : "r"(addr))

#define MMA16816(d, a, b0, b1)                                              \
    asm volatile("mma.sync.aligned.m16n8k16.row.col.f32.bf16.bf16.f32 "     \
                 "{%0,%1,%2,%3}, {%4,%5,%6,%7}, {%8,%9}, {%0,%1,%2,%3};"    \
                 : "+f"((d)[0]), "+f"((d)[1]), "+f"((d)[2]), "+f"((d)[3])   \
                 : "r"((a)[0]), "r"((a)[1]), "r"((a)[2]), "r"((a)[3]),      \
                   "r"(b0), "r"(b1))

// swizzled byte offset inside a 256B-pitch bf16 tile
__device__ __forceinline__ unsigned sw_off(int row, int chunk) {
    return (unsigned)(row * 256 + ((chunk ^ (row & 7)) << 4));
}

// ============================================================================
// Kernel 0: W[128][128] fp32 -> transposed bf16 hi/lo  Wt[n][k]
// ============================================================================
__global__ void wconv_kernel(const float* __restrict__ W) {
    const int idx = blockIdx.x * blockDim.x + threadIdx.x;
    if (idx >= D * D) return;
    const int nrow = idx >> 7;
    const int k    = idx & 127;
    const float w = W[k * D + nrow];
    __nv_bfloat16 hi = __float2bfloat16_rn(w);
    __nv_bfloat16 lo = __float2bfloat16_rn(w - __bfloat162float(hi));
    reinterpret_cast<__nv_bfloat16*>(g_WtHi4)[nrow * D + k] = hi;
    reinterpret_cast<__nv_bfloat16*>(g_WtLo4)[nrow * D + k] = lo;
}

// ============================================================================
// Kernel 1: row aggregation -> bf16 hi/lo split output (one warp per row).
// Processes rows [rbase, rend).
// ============================================================================
__global__ void __launch_bounds__(256)
agg_kernel(const float4* __restrict__ X4,
           const int* __restrict__ rowptr,
           const int* __restrict__ colidx,
           int rbase, int rend) {
    const int w    = rbase + ((blockIdx.x * blockDim.x + threadIdx.x) >> 5);
    const int lane = threadIdx.x & 31;
    if (w >= rend) return;

    int e        = rowptr[w];
    const int e1 = rowptr[w + 1];
    float4 acc = make_float4(0.f, 0.f, 0.f, 0.f);

    for (; e + 8 <= e1; e += 8) {
        float4 v[8];
#pragma unroll
        for (int i = 0; i < 8; i++)
            v[i] = X4[(size_t)colidx[e + i] * 32 + lane];
#pragma unroll
        for (int i = 0; i < 8; i++) {
            acc.x += v[i].x; acc.y += v[i].y;
            acc.z += v[i].z; acc.w += v[i].w;
        }
    }
    for (; e < e1; e++) {
        float4 v = X4[(size_t)colidx[e] * 32 + lane];
        acc.x += v.x; acc.y += v.y; acc.z += v.z; acc.w += v.w;
    }

    unsigned h0, l0, h1, l1;
    split2(acc.x, acc.y, h0, l0);
    split2(acc.z, acc.w, h1, l1);
    reinterpret_cast<uint2*>(g_XpHi4)[(size_t)w * 32 + lane] = make_uint2(h0, h1);
    reinterpret_cast<uint2*>(g_XpLo4)[(size_t)w * 32 + lane] = make_uint2(l0, l1);
}

// ============================================================================
// Kernel 2: split-bf16 GEMM via mma.sync.m16n8k16 (HMMA tensor path).
// Block: 64 rows x 128 cols, 256 threads (8 warps), warp tile 32x32.
// smem: A hi/lo 16KB each + B hi/lo 32KB each = 96KB -> 2 blocks/SM.
// D = Ahi*Bhi + Ahi*Blo + Alo*Bhi, fp32 accumulate.
// ============================================================================
#define BM 64
#define OFF_AHI 0
#define OFF_ALO 16384
#define OFF_BHI 32768
#define OFF_BLO 65536
#define MMA_SMEM 98304

__global__ void __launch_bounds__(256, 2)
mma_kernel(float* __restrict__ out, int rbase, int n) {
    extern __shared__ char smem[];
    const unsigned sb = smem_u32(smem);
    const int tid  = threadIdx.x;
    const int wid  = tid >> 5;
    const int lane = tid & 31;
    const int row0 = rbase + blockIdx.x * BM;

    // ---- Load A tiles (64 rows x 16 chunks of 16B), swizzled ----
#pragma unroll
    for (int u = tid; u < BM * 16; u += 256) {
        const int row = u >> 4;
        const int c   = u & 15;
        const int gr  = row0 + row;
        uint4 vh = make_uint4(0, 0, 0, 0), vl = vh;
        if (gr < n) {
            vh = g_XpHi4[(size_t)gr * 16 + c];
            vl = g_XpLo4[(size_t)gr * 16 + c];
        }
        const unsigned so = sw_off(row, c);
        STS128(sb + OFF_AHI + so, vh);
        STS128(sb + OFF_ALO + so, vl);
    }
    // ---- Load B tiles (128 n-rows x 16 chunks), swizzled ----
#pragma unroll
    for (int u = tid; u < D * 16; u += 256) {
        const int row = u >> 4;
        const int c   = u & 15;
        const uint4 vh = g_WtHi4[u];
        const uint4 vl = g_WtLo4[u];
        const unsigned so = sw_off(row, c);
        STS128(sb + OFF_BHI + so, vh);
        STS128(sb + OFF_BLO + so, vl);
    }
    __syncthreads();

    // warp tile: rows wm*32 (2 m16 tiles), cols wn*32 (4 n8 tiles)
    const int wm = wid >> 2;  // 0..1
    const int wn = wid & 3;   // 0..3

    float acc[2][4][4];
#pragma unroll
    for (int mt = 0; mt < 2; mt++)
#pragma unroll
        for (int nt = 0; nt < 4; nt++)
#pragma unroll
            for (int i = 0; i < 4; i++) acc[mt][nt][i] = 0.f;

    const int lrow = lane & 15;
    const int lch  = lane >> 4;

#pragma unroll 2
    for (int ks = 0; ks < 8; ks++) {
        const int cb = ks * 2 + lch;

        unsigned ah[2][4], al[2][4];
#pragma unroll
        for (int mt = 0; mt < 2; mt++) {
            const int row = wm * 32 + mt * 16 + lrow;
            const unsigned so = sw_off(row, cb);
            LDSM4(ah[mt][0], ah[mt][1], ah[mt][2], ah[mt][3], sb + OFF_AHI + so);
            LDSM4(al[mt][0], al[mt][1], al[mt][2], al[mt][3], sb + OFF_ALO + so);
        }
        unsigned bh[2][4], bl[2][4];
#pragma unroll
        for (int np = 0; np < 2; np++) {
            const int nrow = wn * 32 + np * 16 + lrow;
            const unsigned so = sw_off(nrow, cb);
            LDSM4(bh[np][0], bh[np][1], bh[np][2], bh[np][3], sb + OFF_BHI + so);
            LDSM4(bl[np][0], bl[np][1], bl[np][2], bl[np][3], sb + OFF_BLO + so);
        }

#pragma unroll
        for (int mt = 0; mt < 2; mt++)
#pragma unroll
            for (int nt = 0; nt < 4; nt++) {
                const int np = nt >> 1, hf = nt & 1;
                MMA16816(acc[mt][nt], ah[mt], bh[np][hf], bh[np][hf + 2]);
                MMA16816(acc[mt][nt], ah[mt], bl[np][hf], bl[np][hf + 2]);
                MMA16816(acc[mt][nt], al[mt], bh[np][hf], bh[np][hf + 2]);
            }
    }

    // ---- Epilogue: c0,c1 -> row lane/4; c2,c3 -> row lane/4 + 8 ----
#pragma unroll
    for (int mt = 0; mt < 2; mt++) {
        const int rg = row0 + wm * 32 + mt * 16 + (lane >> 2);
#pragma unroll
        for (int nt = 0; nt < 4; nt++) {
            const int col = wn * 32 + nt * 8 + (lane & 3) * 2;
            if (rg < n)
                *reinterpret_cast<float2*>(&out[(size_t)rg * D + col]) =
                    make_float2(acc[mt][nt][0], acc[mt][nt][1]);
            if (rg + 8 < n)
                *reinterpret_cast<float2*>(&out[(size_t)(rg + 8) * D + col]) =
                    make_float2(acc[mt][nt][2], acc[mt][nt][3]);
        }
    }
}

extern "C" void kernel_launch(void* const* d_in, const int* in_sizes, int n_in,
                              void* d_out, int out_size) {
    const float* X      = (const float*)d_in[0];
    const float* W      = (const float*)d_in[1];
    const int*   rowptr = (const int*)d_in[2];
    const int*   colidx = (const int*)d_in[3];
    float*       out    = (float*)d_out;

    const int n = in_sizes[2] - 1;  // row_pointers has N+1 entries

    // Lazily create side stream + events (first call is the uncaptured
    // correctness run, so no resource creation happens during graph capture).
    static cudaStream_t s2 = nullptr;
    static cudaEvent_t evStart = nullptr, evDone = nullptr;
    static cudaEvent_t evA[NCHUNK];
    if (!s2) {
        cudaStreamCreateWithFlags(&s2, cudaStreamNonBlocking);
        cudaEventCreateWithFlags(&evStart, cudaEventDisableTiming);
        cudaEventCreateWithFlags(&evDone, cudaEventDisableTiming);
        for (int i = 0; i < NCHUNK; i++)
            cudaEventCreateWithFlags(&evA[i], cudaEventDisableTiming);
        cudaFuncSetAttribute(mma_kernel,
                             cudaFuncAttributeMaxDynamicSharedMemorySize,
                             MMA_SMEM);
    }

    // chunk size: multiple of BM
    const int chunkRows = (((n + NCHUNK - 1) / NCHUNK) + BM - 1) & ~(BM - 1);

    // Fork side stream; W conversion runs there (off the critical path).
    cudaEventRecord(evStart, 0);
    cudaStreamWaitEvent(s2, evStart, 0);
    wconv_kernel<<<(D * D + 255) / 256, 256, 0, s2>>>(W);

    for (int c = 0; c < NCHUNK; c++) {
        const int rbase = c * chunkRows;
        if (rbase >= n) {
            // still must signal so the join below is well-formed
            cudaEventRecord(evA[c], 0);
            cudaStreamWaitEvent(s2, evA[c], 0);
            continue;
        }
        const int rend = (rbase + chunkRows < n) ? rbase + chunkRows : n;
        const int rows = rend - rbase;

        // agg chunk on main stream
        const int agrid = (rows * 32 + 255) / 256;
        agg_kernel<<<agrid, 256>>>((const float4*)X, rowptr, colidx, rbase, rend);
        cudaEventRecord(evA[c], 0);

        // mma chunk on side stream, gated on this chunk's aggregation
        cudaStreamWaitEvent(s2, evA[c], 0);
        const int mgrid = (rows + BM - 1) / BM;
        mma_kernel<<<mgrid, 256, MMA_SMEM, s2>>>(out, rbase, n);
    }

    // Join: main stream waits for all mma work
    cudaEventRecord(evDone, s2);
    cudaStreamWaitEvent(0, evDone, 0);
}

// round 10
// speedup vs baseline: 1.0546x; 1.0546x over previous
#include <cuda_runtime.h>
#include <cuda_bf16.h>
#include <cstdint>

#define D 128
#define BM 64
#define NT 512

// smem layout (bytes): A hi 16K | A lo 16K | B hi 32K | B lo 32K
#define OFF_AHI 0
#define OFF_ALO 16384
#define OFF_BHI 32768
#define OFF_BLO 65536
#define FUSE_SMEM 98304

// ---- helpers ----
__device__ __forceinline__ void split2(float a, float b, unsigned& hi, unsigned& lo) {
    __nv_bfloat16 ha = __float2bfloat16_rn(a);
    __nv_bfloat16 hb = __float2bfloat16_rn(b);
    float ra = a - __bfloat162float(ha);
    float rb = b - __bfloat162float(hb);
    __nv_bfloat162 hv; hv.x = ha; hv.y = hb;
    __nv_bfloat162 lv = __floats2bfloat162_rn(ra, rb);
    hi = *reinterpret_cast<unsigned*>(&hv);
    lo = *reinterpret_cast<unsigned*>(&lv);
}

__device__ __forceinline__ unsigned smem_u32(const void* p) {
    unsigned a;
    asm("{ .reg .u64 t; cvta.to.shared.u64 t, %1; cvt.u32.u64 %0, t; }"
        : "=r"(a) : "l"(p));
    return a;
}

#define STS32(addr, v)                                                       \
    asm volatile("st.shared.b32 [%0], %1;" ::"r"(addr), "r"(v) : "memory")

#define STS64(addr, v0, v1)                                                  \
    asm volatile("st.shared.v2.b32 [%0], {%1,%2};" ::"r"(addr), "r"(v0),     \
                 "r"(v1) : "memory")

#define LDSM4(r0, r1, r2, r3, addr)                                          \
    asm volatile("ldmatrix.sync.aligned.m8n8.x4.shared.b16 "                 \
                 "{%0,%1,%2,%3}, [%4];"                                      \
                 : "=r"(r0), "=r"(r1), "=r"(r2), "=r"(r3) : "r"(addr))

#define MMA16816(d, a, b0, b1)                                               \
    asm volatile("mma.sync.aligned.m16n8k16.row.col.f32.bf16.bf16.f32 "      \
                 "{%0,%1,%2,%3}, {%4,%5,%6,%7}, {%8,%9}, {%0,%1,%2,%3};"     \
                 : "+f"((d)[0]), "+f"((d)[1]), "+f"((d)[2]), "+f"((d)[3])    \
                 : "r"((a)[0]), "r"((a)[1]), "r"((a)[2]), "r"((a)[3]),       \
                   "r"(b0), "r"(b1))

#define STG_CS_64(ptr, a, b)                                                 \
    asm volatile("st.global.cs.v2.f32 [%0], {%1,%2};" ::"l"(ptr), "f"(a),    \
                 "f"(b) : "memory")

// swizzled byte offset inside a 256B-pitch bf16 tile (chunk = 16B unit)
__device__ __forceinline__ unsigned sw_off(int row, int chunk) {
    return (unsigned)(row * 256 + ((chunk ^ (row & 7)) << 4));
}

// ============================================================================
// Fused GINConv: per block of 64 destination rows
//  Phase 0: convert W[k][n] fp32 (L1-cached across blocks) -> smem B hi/lo
//           tiles laid out [n][k] bf16 (same layout the R8 kernel proved).
//  Phase 1: gather/aggregate rows, split-bf16 directly into smem A tiles.
//  Phase 2: split-bf16 HMMA: D = Ahi*Bhi + Ahi*Blo + Alo*Bhi (fp32 accum).
// ============================================================================
__global__ void __launch_bounds__(NT, 2)
ginconv_fused(const float4* __restrict__ X4,
              const float* __restrict__ W,
              const int* __restrict__ rowptr,
              const int* __restrict__ colidx,
              float* __restrict__ out,
              int n) {
    extern __shared__ char smem[];
    const unsigned sb = smem_u32(smem);
    const int tid  = threadIdx.x;
    const int wid  = tid >> 5;
    const int lane = tid & 31;
    const int row0 = blockIdx.x * BM;

    // ---- Phase 0: W -> smem B tiles (hi/lo), [n][k] layout, swizzled ----
    // thread t: n-row = t & 127, k-range = (t>>7)*32 .. +32
    {
        const int nrow = tid & 127;
        const int kc   = tid >> 7;  // 0..3
#pragma unroll
        for (int j = 0; j < 16; j++) {
            const int k = kc * 32 + 2 * j;
            const float wa = W[(size_t)k * D + nrow];        // coalesced
            const float wb = W[(size_t)(k + 1) * D + nrow];  // coalesced
            unsigned hi, lo;
            split2(wa, wb, hi, lo);
            const int kp = kc * 16 + j;  // bf16x2 index within row (0..63)
            const unsigned so = (unsigned)(nrow * 256) +
                                ((unsigned)(((kp >> 2) ^ (nrow & 7)) << 4)) +
                                (unsigned)((kp & 3) * 4);
            STS32(sb + OFF_BHI + so, hi);
            STS32(sb + OFF_BLO + so, lo);
        }
    }

    // ---- Phase 1: gather 4 rows per warp into smem A tiles ----
#pragma unroll 1
    for (int t = 0; t < 4; t++) {
        const int lr = wid * 4 + t;
        const int r  = row0 + lr;
        float4 acc = make_float4(0.f, 0.f, 0.f, 0.f);
        if (r < n) {
            int e        = rowptr[r];
            const int e1 = rowptr[r + 1];
            for (; e + 8 <= e1; e += 8) {
                float4 v[8];
#pragma unroll
                for (int i = 0; i < 8; i++)
                    v[i] = X4[(size_t)colidx[e + i] * 32 + lane];
#pragma unroll
                for (int i = 0; i < 8; i++) {
                    acc.x += v[i].x; acc.y += v[i].y;
                    acc.z += v[i].z; acc.w += v[i].w;
                }
            }
            for (; e < e1; e++) {
                float4 v = X4[(size_t)colidx[e] * 32 + lane];
                acc.x += v.x; acc.y += v.y; acc.z += v.z; acc.w += v.w;
            }
        }
        unsigned h0, l0, h1, l1;
        split2(acc.x, acc.y, h0, l0);
        split2(acc.z, acc.w, h1, l1);
        // lane owns features 4*lane..4*lane+3 -> bf16x2 pairs 2*lane, 2*lane+1
        const unsigned so = (unsigned)(lr * 256) +
                            ((unsigned)(((lane >> 1) ^ (lr & 7)) << 4)) +
                            (unsigned)((lane & 1) * 8);
        STS64(sb + OFF_AHI + so, h0, h1);
        STS64(sb + OFF_ALO + so, l0, l1);
    }
    __syncthreads();

    // ---- Phase 2: HMMA. 16 warps, warp tile 16 rows x 32 cols ----
    const int wm = wid >> 2;  // 0..3 : rows wm*16 .. +15
    const int wn = wid & 3;   // 0..3 : cols wn*32 .. +31

    float acc[4][4];
#pragma unroll
    for (int nt = 0; nt < 4; nt++)
#pragma unroll
        for (int i = 0; i < 4; i++) acc[nt][i] = 0.f;

    const int lrow = lane & 15;
    const int lch  = lane >> 4;

#pragma unroll 2
    for (int ks = 0; ks < 8; ks++) {
        const int cb = ks * 2 + lch;

        unsigned ah[4], al[4];
        {
            const unsigned so = sw_off(wm * 16 + lrow, cb);
            LDSM4(ah[0], ah[1], ah[2], ah[3], sb + OFF_AHI + so);
            LDSM4(al[0], al[1], al[2], al[3], sb + OFF_ALO + so);
        }
#pragma unroll
        for (int np = 0; np < 2; np++) {
            unsigned bh[4], bl[4];
            const unsigned so = sw_off(wn * 32 + np * 16 + lrow, cb);
            LDSM4(bh[0], bh[1], bh[2], bh[3], sb + OFF_BHI + so);
            LDSM4(bl[0], bl[1], bl[2], bl[3], sb + OFF_BLO + so);
#pragma unroll
            for (int hf = 0; hf < 2; hf++) {
                const int nt = np * 2 + hf;
                MMA16816(acc[nt], ah, bh[hf], bh[hf + 2]);
                MMA16816(acc[nt], ah, bl[hf], bl[hf + 2]);
                MMA16816(acc[nt], al, bh[hf], bh[hf + 2]);
            }
        }
    }

    // ---- Epilogue ----
    {
        const int rg = row0 + wm * 16 + (lane >> 2);
#pragma unroll
        for (int nt = 0; nt < 4; nt++) {
            const int col = wn * 32 + nt * 8 + (lane & 3) * 2;
            if (rg < n)
                STG_CS_64(&out[(size_t)rg * D + col], acc[nt][0], acc[nt][1]);
            if (rg + 8 < n)
                STG_CS_64(&out[(size_t)(rg + 8) * D + col], acc[nt][2],
                          acc[nt][3]);
        }
    }
}

extern "C" void kernel_launch(void* const* d_in, const int* in_sizes, int n_in,
                              void* d_out, int out_size) {
    const float* X      = (const float*)d_in[0];
    const float* W      = (const float*)d_in[1];
    const int*   rowptr = (const int*)d_in[2];
    const int*   colidx = (const int*)d_in[3];
    float*       out    = (float*)d_out;

    const int n = in_sizes[2] - 1;  // row_pointers has N+1 entries

    cudaFuncSetAttribute(ginconv_fused,
                         cudaFuncAttributeMaxDynamicSharedMemorySize,
                         FUSE_SMEM);

    const int grid = (n + BM - 1) / BM;
    ginconv_fused<<<grid, NT, FUSE_SMEM>>>((const float4*)X, W, rowptr, colidx,
                                           out, n);
}

// round 11
// speedup vs baseline: 1.1329x; 1.0743x over previous
#include <cuda_runtime.h>
#include <cuda_bf16.h>
#include <cstdint>

#define D 128
#define BM 64
#define NT 512

// smem layout (bytes): A hi 16K | A lo 16K | B hi 32K | B lo 32K
#define OFF_AHI 0
#define OFF_ALO 16384
#define OFF_BHI 32768
#define OFF_BLO 65536
#define FUSE_SMEM 98304

// ---- helpers ----
__device__ __forceinline__ void split2(float a, float b, unsigned& hi, unsigned& lo) {
    __nv_bfloat16 ha = __float2bfloat16_rn(a);
    __nv_bfloat16 hb = __float2bfloat16_rn(b);
    float ra = a - __bfloat162float(ha);
    float rb = b - __bfloat162float(hb);
    __nv_bfloat162 hv; hv.x = ha; hv.y = hb;
    __nv_bfloat162 lv = __floats2bfloat162_rn(ra, rb);
    hi = *reinterpret_cast<unsigned*>(&hv);
    lo = *reinterpret_cast<unsigned*>(&lv);
}

__device__ __forceinline__ unsigned smem_u32(const void* p) {
    unsigned a;
    asm("{ .reg .u64 t; cvta.to.shared.u64 t, %1; cvt.u32.u64 %0, t; }"
        : "=r"(a) : "l"(p));
    return a;
}

#define STS64(addr, v0, v1)                                                  \
    asm volatile("st.shared.v2.b32 [%0], {%1,%2};" ::"r"(addr), "r"(v0),     \
                 "r"(v1) : "memory")

#define STS128V(addr, v0, v1, v2, v3)                                        \
    asm volatile("st.shared.v4.b32 [%0], {%1,%2,%3,%4};" ::"r"(addr),        \
                 "r"(v0), "r"(v1), "r"(v2), "r"(v3) : "memory")

#define LDSM4(r0, r1, r2, r3, addr)                                          \
    asm volatile("ldmatrix.sync.aligned.m8n8.x4.shared.b16 "                 \
                 "{%0,%1,%2,%3}, [%4];"                                      \
                 : "=r"(r0), "=r"(r1), "=r"(r2), "=r"(r3) : "r"(addr))

#define MMA16816(d, a, b0, b1)                                               \
    asm volatile("mma.sync.aligned.m16n8k16.row.col.f32.bf16.bf16.f32 "      \
                 "{%0,%1,%2,%3}, {%4,%5,%6,%7}, {%8,%9}, {%0,%1,%2,%3};"     \
                 : "+f"((d)[0]), "+f"((d)[1]), "+f"((d)[2]), "+f"((d)[3])    \
                 : "r"((a)[0]), "r"((a)[1]), "r"((a)[2]), "r"((a)[3]),       \
                   "r"(b0), "r"(b1))

#define STG_CS_64(ptr, a, b)                                                 \
    asm volatile("st.global.cs.v2.f32 [%0], {%1,%2};" ::"l"(ptr), "f"(a),    \
                 "f"(b) : "memory")

// swizzled byte offset inside a 256B-pitch bf16 tile (chunk = 16B unit)
__device__ __forceinline__ unsigned sw_off(int row, int chunk) {
    return (unsigned)(row * 256 + ((chunk ^ (row & 7)) << 4));
}

// ============================================================================
// Fused GINConv: per block of 64 destination rows
//  Phase 0: W[k][n] fp32 (L1-hot) -> smem B hi/lo tiles [n][k] bf16 via
//           conflict-free STS128 (R10 used STS32 with 32-way conflicts!)
//  Phase 1: gather/aggregate rows, split-bf16 directly into smem A tiles.
//  Phase 2: split-bf16 HMMA: D = Ahi*Bhi + Ahi*Blo + Alo*Bhi (fp32 accum).
// ============================================================================
__global__ void __launch_bounds__(NT, 2)
ginconv_fused(const float4* __restrict__ X4,
              const float* __restrict__ W,
              const int* __restrict__ rowptr,
              const int* __restrict__ colidx,
              float* __restrict__ out,
              int n) {
    extern __shared__ char smem[];
    const unsigned sb = smem_u32(smem);
    const int tid  = threadIdx.x;
    const int wid  = tid >> 5;
    const int lane = tid & 31;
    const int row0 = blockIdx.x * BM;

    // ---- Phase 0: W -> smem B tiles (hi/lo), [n][k] bf16, swizzled ----
    // thread t: nrow = t & 127 (lanes -> consecutive rows, coalesced LDG,
    // swizzle spreads banks); chunks c = (t>>7)*4 .. +3, chunk = 8 k-values.
    {
        const int nrow = tid & 127;
        const int g    = tid >> 7;  // 0..3
#pragma unroll
        for (int c8 = 0; c8 < 4; c8++) {
            const int c = g * 4 + c8;  // 16B chunk index 0..15
            unsigned hi[4], lo[4];
#pragma unroll
            for (int p = 0; p < 4; p++) {
                const int k = c * 8 + p * 2;
                const float wa = W[(size_t)k * D + nrow];
                const float wb = W[(size_t)(k + 1) * D + nrow];
                split2(wa, wb, hi[p], lo[p]);
            }
            const unsigned so = sw_off(nrow, c);
            STS128V(sb + OFF_BHI + so, hi[0], hi[1], hi[2], hi[3]);
            STS128V(sb + OFF_BLO + so, lo[0], lo[1], lo[2], lo[3]);
        }
    }

    // ---- Phase 1: gather 4 rows per warp into smem A tiles ----
#pragma unroll 1
    for (int t = 0; t < 4; t++) {
        const int lr = wid * 4 + t;
        const int r  = row0 + lr;
        float4 acc = make_float4(0.f, 0.f, 0.f, 0.f);
        if (r < n) {
            int e        = rowptr[r];
            const int e1 = rowptr[r + 1];
            for (; e + 8 <= e1; e += 8) {
                float4 v[8];
#pragma unroll
                for (int i = 0; i < 8; i++)
                    v[i] = X4[(size_t)colidx[e + i] * 32 + lane];
#pragma unroll
                for (int i = 0; i < 8; i++) {
                    acc.x += v[i].x; acc.y += v[i].y;
                    acc.z += v[i].z; acc.w += v[i].w;
                }
            }
            for (; e < e1; e++) {
                float4 v = X4[(size_t)colidx[e] * 32 + lane];
                acc.x += v.x; acc.y += v.y; acc.z += v.z; acc.w += v.w;
            }
        }
        unsigned h0, l0, h1, l1;
        split2(acc.x, acc.y, h0, l0);
        split2(acc.z, acc.w, h1, l1);
        // lane owns features 4*lane..4*lane+3 -> 8B at chunk lane>>1
        const unsigned so = (unsigned)(lr * 256) +
                            ((unsigned)(((lane >> 1) ^ (lr & 7)) << 4)) +
                            (unsigned)((lane & 1) * 8);
        STS64(sb + OFF_AHI + so, h0, h1);
        STS64(sb + OFF_ALO + so, l0, l1);
    }
    __syncthreads();

    // ---- Phase 2: HMMA. 16 warps, warp tile 16 rows x 32 cols ----
    const int wm = wid >> 2;  // 0..3 : rows wm*16 .. +15
    const int wn = wid & 3;   // 0..3 : cols wn*32 .. +31

    float acc[4][4];
#pragma unroll
    for (int nt = 0; nt < 4; nt++)
#pragma unroll
        for (int i = 0; i < 4; i++) acc[nt][i] = 0.f;

    const int lrow = lane & 15;
    const int lch  = lane >> 4;

#pragma unroll 2
    for (int ks = 0; ks < 8; ks++) {
        const int cb = ks * 2 + lch;

        unsigned ah[4], al[4];
        {
            const unsigned so = sw_off(wm * 16 + lrow, cb);
            LDSM4(ah[0], ah[1], ah[2], ah[3], sb + OFF_AHI + so);
            LDSM4(al[0], al[1], al[2], al[3], sb + OFF_ALO + so);
        }
#pragma unroll
        for (int np = 0; np < 2; np++) {
            unsigned bh[4], bl[4];
            const unsigned so = sw_off(wn * 32 + np * 16 + lrow, cb);
            LDSM4(bh[0], bh[1], bh[2], bh[3], sb + OFF_BHI + so);
            LDSM4(bl[0], bl[1], bl[2], bl[3], sb + OFF_BLO + so);
#pragma unroll
            for (int hf = 0; hf < 2; hf++) {
                const int nt = np * 2 + hf;
                MMA16816(acc[nt], ah, bh[hf], bh[hf + 2]);
                MMA16816(acc[nt], ah, bl[hf], bl[hf + 2]);
                MMA16816(acc[nt], al, bh[hf], bh[hf + 2]);
            }
        }
    }

    // ---- Epilogue ----
    {
        const int rg = row0 + wm * 16 + (lane >> 2);
#pragma unroll
        for (int nt = 0; nt < 4; nt++) {
            const int col = wn * 32 + nt * 8 + (lane & 3) * 2;
            if (rg < n)
                STG_CS_64(&out[(size_t)rg * D + col], acc[nt][0], acc[nt][1]);
            if (rg + 8 < n)
                STG_CS_64(&out[(size_t)(rg + 8) * D + col], acc[nt][2],
                          acc[nt][3]);
        }
    }
}

extern "C" void kernel_launch(void* const* d_in, const int* in_sizes, int n_in,
                              void* d_out, int out_size) {
    const float* X      = (const float*)d_in[0];
    const float* W      = (const float*)d_in[1];
    const int*   rowptr = (const int*)d_in[2];
    const int*   colidx = (const int*)d_in[3];
    float*       out    = (float*)d_out;

    const int n = in_sizes[2] - 1;  // row_pointers has N+1 entries

    cudaFuncSetAttribute(ginconv_fused,
                         cudaFuncAttributeMaxDynamicSharedMemorySize,
                         FUSE_SMEM);

    const int grid = (n + BM - 1) / BM;
    ginconv_fused<<<grid, NT, FUSE_SMEM>>>((const float4*)X, W, rowptr, colidx,
                                           out, n);
}